// round 11
// baseline (speedup 1.0000x reference)
#include <cuda_runtime.h>
#include <cuda_bf16.h>
#include <cstdint>
#include <cstddef>

// Problem constants (fixed by the dataset)
#define BSZ 8
#define LSEQ 4096
#define DM 1024
#define NS 64
#define CT 128
#define NC (LSEQ / CT)
#define LN_EPS 1e-5f

// ---------------- device scratch ----------------
__device__ float2 g_abar[NS];
__device__ float2 g_apow[(CT + 1) * NS];
__device__ __nv_bfloat16 g_Wh[128 * DM];          // [j][k] bf16; j<64 Re, j>=64 Im
__device__ float  g_Ct[DM * NS];                  // warp-contiguous tf32 C fragments
__device__ float  g_hr[(size_t)BSZ * LSEQ * NS];  // within-chunk scanned states (REAL only)
__device__ float2 g_last[BSZ * NC * NS];          // chunk-final local states (complex)
__device__ float2 g_carry[BSZ * NC * NS];         // carry-in per chunk (complex)

__device__ __forceinline__ float2 cmul(float2 a, float2 b) {
    return make_float2(a.x * b.x - a.y * b.y, a.x * b.y + a.y * b.x);
}
__device__ __forceinline__ uint32_t f2tf(float f) {
    uint32_t r;
    asm("cvt.rna.tf32.f32 %0, %1;" : "=r"(r) : "f"(f));
    return r;
}
__device__ __forceinline__ uint32_t f2bf2(float lo, float hi) {
    __nv_bfloat162 h = __floats2bfloat162_rn(lo, hi);   // lo -> .x (low half)
    return *(uint32_t*)&h;
}
// tf32 m16n8k8 (used by k3)
__device__ __forceinline__ void mma8(float4& d, const uint32_t* a, const uint32_t* b) {
    asm volatile(
        "mma.sync.aligned.m16n8k8.row.col.f32.tf32.tf32.f32 "
        "{%0,%1,%2,%3},{%4,%5,%6,%7},{%8,%9},{%0,%1,%2,%3};\n"
        : "+f"(d.x), "+f"(d.y), "+f"(d.z), "+f"(d.w)
        : "r"(a[0]), "r"(a[1]), "r"(a[2]), "r"(a[3]), "r"(b[0]), "r"(b[1]));
}
// bf16 m16n8k16 (used by k1)
__device__ __forceinline__ void mma16bf(float4& d, const uint32_t* a, const uint32_t* b) {
    asm volatile(
        "mma.sync.aligned.m16n8k16.row.col.f32.bf16.bf16.f32 "
        "{%0,%1,%2,%3},{%4,%5,%6,%7},{%8,%9},{%0,%1,%2,%3};\n"
        : "+f"(d.x), "+f"(d.y), "+f"(d.z), "+f"(d.w)
        : "r"(a[0]), "r"(a[1]), "r"(a[2]), "r"(a[3]), "r"(b[0]), "r"(b[1]));
}

// ---------------- K0: constants + W build (bf16) + C fragment permute ----------------
// blocks 0..127   : Wh[j][k] bf16; block 0 also writes abar/apow tables
// blocks 128..383 : g_Ct warp-contiguous layout (uint4 index i = o>>2):
//   i = s*1024 + nt*128 + ksb*32 + lane   (s = 64-row d slice, lane = lq*4+cq)
//   maps to d = s*64 + nt*8 + lq,  k = 8*(2*ksb + (q>>1)) + cq + 4*(q&1)
__global__ void k0_prep(const float* __restrict__ lnr, const float* __restrict__ imag,
                        const float* __restrict__ Bm, const float* __restrict__ Cm) {
    int j = blockIdx.x;
    int tid = threadIdx.x;
    if (j < 128) {
        int n = j & 63;
        float ar = -expf(lnr[n]);
        float ai = imag[n];
        float e  = expf(ar);
        float2 abar = make_float2(e * cosf(ai), e * sinf(ai));
        float2 num = make_float2(abar.x - 1.0f, abar.y);
        float inv = 1.0f / (ar * ar + ai * ai);
        float2 coef = make_float2((num.x * ar + num.y * ai) * inv,
                                  (num.y * ar - num.x * ai) * inv);
        float s = (j < NS) ? coef.x : coef.y;
        for (int k = tid; k < DM; k += blockDim.x)
            g_Wh[(size_t)j * DM + k] = __float2bfloat16_rn(s * Bm[(size_t)n * DM + k]);
        if (j == 0 && tid < NS) {
            int nn = tid;
            float ar2 = -expf(lnr[nn]);
            float ai2 = imag[nn];
            float e2  = expf(ar2);
            float2 ab = make_float2(e2 * cosf(ai2), e2 * sinf(ai2));
            g_abar[nn] = ab;
            float2 p = make_float2(1.0f, 0.0f);
            for (int k = 0; k <= CT; k++) {
                g_apow[k * NS + nn] = p;
                p = cmul(p, ab);
            }
        }
    } else {
        int o = (j - 128) * 256 + tid;       // 0..65535
        int q    = o & 3;
        int lane = (o >> 2) & 31;
        int ksb  = (o >> 7) & 3;
        int nt   = (o >> 9) & 7;
        int s    = o >> 12;                  // 0..15
        int cq = lane & 3, lq = lane >> 2;
        int d = s * 64 + nt * 8 + lq;
        int k = 8 * (2 * ksb + (q >> 1)) + cq + 4 * (q & 1);
        g_Ct[o] = __uint_as_float(f2tf(Cm[(size_t)d * NS + k]));
    }
}

// ---------------- K1: bf16 MMA Bu-GEMM (128x128, K=1024) + local scan ----------------
// smem: bf16 tiles, 40 bf16/row (80B): fragment word idx = r*20 + ks*8 + cq
// -> banks lq*20+cq mod 32 = conflict-free. Bu (64KB fp32) aliases the tiles.
#define KC 32
#define HSTR 40                 // bf16 units per row
#define K1_SMEM 65536           // Bu 128*128*4 = 64KB dominates (tiles = 40KB)

__global__ __launch_bounds__(256, 2) void k1_bu_scan(const float* __restrict__ u) {
    extern __shared__ char smc[];
    __nv_bfloat16* As0 = (__nv_bfloat16*)smc;                    // 10240B each
    __nv_bfloat16* As1 = (__nv_bfloat16*)(smc + 10240);
    __nv_bfloat16* Bs0 = (__nv_bfloat16*)(smc + 20480);
    __nv_bfloat16* Bs1 = (__nv_bfloat16*)(smc + 30720);
    float* Bu = (float*)smc;                                     // alias, used after mainloop

    int chunk = blockIdx.x, b = blockIdx.y;
    int tid = threadIdx.x;
    int lane = tid & 31, warp = tid >> 5;
    int wm = warp & 1, wn = warp >> 1;
    int m0 = wm * 64, n0 = wn * 32;
    int lq = lane >> 2, cq = lane & 3;

    const float* up = u + ((size_t)(b * LSEQ + chunk * CT)) * DM;

    float4 acc[4][4];
#pragma unroll
    for (int i = 0; i < 4; i++)
#pragma unroll
        for (int j = 0; j < 4; j++) acc[i][j] = make_float4(0.f, 0.f, 0.f, 0.f);

    float4 rA[4];
    uint2  rW[4];
    int lrow[4], lkq[4];
#pragma unroll
    for (int i = 0; i < 4; i++) {
        int lin = tid + i * 256;
        lrow[i] = lin >> 3;          // 0..127
        lkq[i] = (lin & 7) * 4;      // 0,4,...,28
    }

    // preload stage 0
#pragma unroll
    for (int i = 0; i < 4; i++) {
        rA[i] = *(const float4*)(up + (size_t)lrow[i] * DM + lkq[i]);
        rW[i] = *(const uint2*)(g_Wh + (size_t)lrow[i] * DM + lkq[i]);
    }
#pragma unroll
    for (int i = 0; i < 4; i++) {
        uint2 a;
        a.x = f2bf2(rA[i].x, rA[i].y);
        a.y = f2bf2(rA[i].z, rA[i].w);
        *(uint2*)(As0 + lrow[i] * HSTR + lkq[i]) = a;
        *(uint2*)(Bs0 + lrow[i] * HSTR + lkq[i]) = rW[i];
    }
    __syncthreads();

    for (int s = 0; s < DM / KC; s++) {
        __nv_bfloat16* Ac = (s & 1) ? As1 : As0;
        __nv_bfloat16* Bc = (s & 1) ? Bs1 : Bs0;
        __nv_bfloat16* An = (s & 1) ? As0 : As1;
        __nv_bfloat16* Bn = (s & 1) ? Bs0 : Bs1;
        if (s + 1 < DM / KC) {
            int k0 = (s + 1) * KC;
#pragma unroll
            for (int i = 0; i < 4; i++) {
                rA[i] = *(const float4*)(up + (size_t)lrow[i] * DM + k0 + lkq[i]);
                rW[i] = *(const uint2*)(g_Wh + (size_t)lrow[i] * DM + k0 + lkq[i]);
            }
        }
        const uint32_t* Au = (const uint32_t*)Ac;   // 20 words per row
        const uint32_t* Bv = (const uint32_t*)Bc;
#pragma unroll
        for (int ks = 0; ks < 2; ks++) {            // two k16 steps per stage
            int kb = ks * 8;
            uint32_t af[4][4], bf[4][2];
#pragma unroll
            for (int mt = 0; mt < 4; mt++) {
                int r = m0 + mt * 16 + lq;
                af[mt][0] = Au[r * 20 + kb + cq];
                af[mt][1] = Au[(r + 8) * 20 + kb + cq];
                af[mt][2] = Au[r * 20 + kb + cq + 4];
                af[mt][3] = Au[(r + 8) * 20 + kb + cq + 4];
            }
#pragma unroll
            for (int nt = 0; nt < 4; nt++) {
                int c = n0 + nt * 8 + lq;
                bf[nt][0] = Bv[c * 20 + kb + cq];
                bf[nt][1] = Bv[c * 20 + kb + cq + 4];
            }
#pragma unroll
            for (int mt = 0; mt < 4; mt++)
#pragma unroll
                for (int nt = 0; nt < 4; nt++)
                    mma16bf(acc[mt][nt], af[mt], bf[nt]);
        }
        if (s + 1 < DM / KC) {
#pragma unroll
            for (int i = 0; i < 4; i++) {
                uint2 a;
                a.x = f2bf2(rA[i].x, rA[i].y);
                a.y = f2bf2(rA[i].z, rA[i].w);
                *(uint2*)(An + lrow[i] * HSTR + lkq[i]) = a;
                *(uint2*)(Bn + lrow[i] * HSTR + lkq[i]) = rW[i];
            }
        }
        __syncthreads();
    }

    // write Bu tile to smem (aliases the bf16 tiles — all reads done at last sync)
#pragma unroll
    for (int mt = 0; mt < 4; mt++) {
        int r = m0 + mt * 16 + lq;
#pragma unroll
        for (int nt = 0; nt < 4; nt++) {
            int c = n0 + nt * 8 + cq * 2;
            *(float2*)(Bu + r * 128 + c)       = make_float2(acc[mt][nt].x, acc[mt][nt].y);
            *(float2*)(Bu + (r + 8) * 128 + c) = make_float2(acc[mt][nt].z, acc[mt][nt].w);
        }
    }
    __syncthreads();

    // local scan: 64 states, 1 thread each; store REAL part only
    if (tid < NS) {
        float2 ab = g_abar[tid];
        float hr = 0.0f, hi = 0.0f;
        float* outp = g_hr + ((size_t)(b * LSEQ + chunk * CT)) * NS + tid;
#pragma unroll 4
        for (int t = 0; t < CT; t++) {
            float xr = Bu[t * 128 + tid];
            float xi = Bu[t * 128 + 64 + tid];
            float nr = fmaf(ab.x, hr, fmaf(-ab.y, hi, xr));
            float ni = fmaf(ab.x, hi, fmaf( ab.y, hr, xi));
            hr = nr; hi = ni;
            outp[(size_t)t * NS] = hr;
        }
        g_last[(b * NC + chunk) * NS + tid] = make_float2(hr, hi);
    }
}

// ---------------- K2: cross-chunk carry scan (8 blocks, prefetched) ----------------
__global__ void k2_carry() {
    int b = blockIdx.x;          // 8 blocks
    int n = threadIdx.x;         // 64 threads
    float2 p = g_apow[CT * NS + n];
    float2 S[NC];
#pragma unroll
    for (int c = 0; c < NC; c++) S[c] = g_last[(b * NC + c) * NS + n];
    float2 H = make_float2(0.0f, 0.0f);
#pragma unroll
    for (int c = 0; c < NC; c++) {
        g_carry[(b * NC + c) * NS + n] = H;
        float2 t = cmul(p, H);
        H = make_float2(t.x + S[c].x, t.y + S[c].y);
    }
}

// ---------------- K3: mma readout -> smem exchange -> coalesced residual+LN ----------------
// (proven R9 form: 512 threads, 32 tokens/block, warp owns 64-wide d-slice)
#define XSTR 1036
#define K3_SMEM ((32 * 68 + 32 * XSTR) * 4)

__global__ __launch_bounds__(512, 1) void k3_readout(const float* __restrict__ u,
                                                     const float* __restrict__ Dv,
                                                     const float* __restrict__ gamma,
                                                     const float* __restrict__ beta,
                                                     float* __restrict__ out) {
    extern __shared__ float sm3[];
    float* Rs = sm3;                 // [32][68] tf32 bits
    float* X  = sm3 + 32 * 68;       // [32][XSTR] y values

    int g = blockIdx.x, b = blockIdx.y;
    int chunk = g >> 2, t0 = (g & 3) * 32;
    int tid = threadIdx.x;
    int lane = tid & 31, warp = tid >> 5;
    int lq = lane >> 2, cq = lane & 3;
    size_t tokbase = (size_t)b * LSEQ + (size_t)chunk * CT + t0;

    // build Rs[t][n] = tf32(Re(a^{t0+t+1} * H) + hr_local)
    {
        int n = tid & 63, tq = tid >> 6;    // 8 token groups
        float2 H = g_carry[(b * NC + chunk) * NS + n];
        const float* hp = g_hr + tokbase * NS;
#pragma unroll
        for (int t = tq; t < 32; t += 8) {
            float lv = hp[(size_t)t * NS + n];
            float2 pw = g_apow[(t0 + t + 1) * NS + n];
            float v = fmaf(pw.x, H.x, fmaf(-pw.y, H.y, lv));
            Rs[t * 68 + n] = __uint_as_float(f2tf(v));
        }
    }
    __syncthreads();

    float4 acc[2][8];
#pragma unroll
    for (int mt = 0; mt < 2; mt++)
#pragma unroll
        for (int nt = 0; nt < 8; nt++) acc[mt][nt] = make_float4(0.f, 0.f, 0.f, 0.f);

    const uint32_t* Ru = (const uint32_t*)Rs;
    const uint4* Ct = (const uint4*)g_Ct;   // i = warp*1024 + nt*128 + ksb*32 + lane
    int cbase = warp * 1024 + lane;

#pragma unroll
    for (int ksb = 0; ksb < 4; ksb++) {
        uint32_t af[2][2][4];
#pragma unroll
        for (int ko = 0; ko < 2; ko++) {
            int kb = (ksb * 2 + ko) * 8;
#pragma unroll
            for (int mt = 0; mt < 2; mt++) {
                int r = mt * 16 + lq;
                af[ko][mt][0] = Ru[r * 68 + kb + cq];
                af[ko][mt][1] = Ru[(r + 8) * 68 + kb + cq];
                af[ko][mt][2] = Ru[r * 68 + kb + cq + 4];
                af[ko][mt][3] = Ru[(r + 8) * 68 + kb + cq + 4];
            }
        }
        uint4 Cf = Ct[cbase + ksb * 32];
#pragma unroll
        for (int nt = 0; nt < 8; nt++) {
            uint4 cur = Cf;
            if (nt < 7)
                Cf = Ct[cbase + (nt + 1) * 128 + ksb * 32];
            uint32_t b0[2] = {cur.x, cur.y};
            uint32_t b1[2] = {cur.z, cur.w};
#pragma unroll
            for (int mt = 0; mt < 2; mt++) {
                mma8(acc[mt][nt], af[0][mt], b0);
                mma8(acc[mt][nt], af[1][mt], b1);
            }
        }
    }

    // stage y into X
    int d0w = warp * 64;
#pragma unroll
    for (int nt = 0; nt < 8; nt++) {
        int d = d0w + nt * 8 + cq * 2;
#pragma unroll
        for (int mt = 0; mt < 2; mt++) {
            int r1 = mt * 16 + lq;
            *(float2*)(X + r1 * XSTR + d)       = make_float2(acc[mt][nt].x, acc[mt][nt].y);
            *(float2*)(X + (r1 + 8) * XSTR + d) = make_float2(acc[mt][nt].z, acc[mt][nt].w);
        }
    }
    __syncthreads();

    // coalesced residual + LN: warp w handles token rows 2w, 2w+1
#pragma unroll
    for (int rr = 0; rr < 2; rr++) {
        int r = warp * 2 + rr;
        const float* up = u + (tokbase + r) * DM;
        float* op = out + (tokbase + r) * DM;
        float4 xv[8];
        float s = 0.f, q = 0.f;
#pragma unroll
        for (int i = 0; i < 8; i++) {
            int d = (lane + i * 32) * 4;
            float4 uu = *(const float4*)(up + d);
            float4 D4 = *(const float4*)(Dv + d);
            float4 y  = *(float4*)(X + r * XSTR + d);
            float4 x;
            x.x = fmaf(uu.x, 1.0f + D4.x, y.x);
            x.y = fmaf(uu.y, 1.0f + D4.y, y.y);
            x.z = fmaf(uu.z, 1.0f + D4.z, y.z);
            x.w = fmaf(uu.w, 1.0f + D4.w, y.w);
            xv[i] = x;
            s += x.x + x.y + x.z + x.w;
            q += x.x * x.x + x.y * x.y + x.z * x.z + x.w * x.w;
        }
#pragma unroll
        for (int o = 16; o > 0; o >>= 1) {
            s += __shfl_xor_sync(0xffffffffu, s, o);
            q += __shfl_xor_sync(0xffffffffu, q, o);
        }
        float mu = s * (1.0f / DM);
        float var = q * (1.0f / DM) - mu * mu;
        float rstd = rsqrtf(var + LN_EPS);
#pragma unroll
        for (int i = 0; i < 8; i++) {
            int d = (lane + i * 32) * 4;
            float4 gg = *(const float4*)(gamma + d);
            float4 bb = *(const float4*)(beta + d);
            float4 v = xv[i], o4;
            o4.x = fmaf((v.x - mu) * rstd, gg.x, bb.x);
            o4.y = fmaf((v.y - mu) * rstd, gg.y, bb.y);
            o4.z = fmaf((v.z - mu) * rstd, gg.z, bb.z);
            o4.w = fmaf((v.w - mu) * rstd, gg.w, bb.w);
            *(float4*)(op + d) = o4;
        }
    }
}

// ---------------- launch ----------------
extern "C" void kernel_launch(void* const* d_in, const int* in_sizes, int n_in,
                              void* d_out, int out_size) {
    const float* u     = (const float*)d_in[0];
    const float* lnr   = (const float*)d_in[1];
    const float* imagv = (const float*)d_in[2];
    const float* Bm    = (const float*)d_in[3];
    const float* Cm    = (const float*)d_in[4];
    const float* Dv    = (const float*)d_in[5];
    const float* gamma = (const float*)d_in[6];
    const float* beta  = (const float*)d_in[7];
    float* out = (float*)d_out;

    cudaFuncSetAttribute(k1_bu_scan, cudaFuncAttributeMaxDynamicSharedMemorySize, K1_SMEM);
    cudaFuncSetAttribute(k3_readout, cudaFuncAttributeMaxDynamicSharedMemorySize, K3_SMEM);

    k0_prep<<<384, 256>>>(lnr, imagv, Bm, Cm);
    k1_bu_scan<<<dim3(NC, BSZ), 256, K1_SMEM>>>(u);
    k2_carry<<<8, 64>>>();
    k3_readout<<<dim3(NC * 4, BSZ), 512, K3_SMEM>>>(u, Dv, gamma, beta, out);
}

// round 12
// speedup vs baseline: 1.4288x; 1.4288x over previous
#include <cuda_runtime.h>
#include <cuda_bf16.h>
#include <cstdint>
#include <cstddef>

// Problem constants (fixed by the dataset)
#define BSZ 8
#define LSEQ 4096
#define DM 1024
#define NS 64
#define CT 128
#define NC (LSEQ / CT)
#define LN_EPS 1e-5f

// ---------------- device scratch ----------------
__device__ float2 g_abar[NS];
__device__ float2 g_apow[(CT + 1) * NS];
__device__ __nv_bfloat16 g_Wh[128 * DM];          // [j][k] bf16; j<64 Re, j>=64 Im
__device__ float  g_Ct[DM * NS];                  // warp-contiguous tf32 C fragments
__device__ float  g_hr[(size_t)BSZ * LSEQ * NS];  // within-chunk scanned states (REAL only)
__device__ float2 g_last[BSZ * NC * NS];          // chunk-final local states (complex)
__device__ float2 g_carry[BSZ * NC * NS];         // carry-in per chunk (complex)

__device__ __forceinline__ float2 cmul(float2 a, float2 b) {
    return make_float2(a.x * b.x - a.y * b.y, a.x * b.y + a.y * b.x);
}
__device__ __forceinline__ uint32_t f2tf(float f) {
    uint32_t r;
    asm("cvt.rna.tf32.f32 %0, %1;" : "=r"(r) : "f"(f));
    return r;
}
__device__ __forceinline__ uint32_t f2bf2(float lo, float hi) {
    __nv_bfloat162 h = __floats2bfloat162_rn(lo, hi);   // lo -> .x (low half)
    return *(uint32_t*)&h;
}
// tf32 m16n8k8 (used by k3)
__device__ __forceinline__ void mma8(float4& d, const uint32_t* a, const uint32_t* b) {
    asm volatile(
        "mma.sync.aligned.m16n8k8.row.col.f32.tf32.tf32.f32 "
        "{%0,%1,%2,%3},{%4,%5,%6,%7},{%8,%9},{%0,%1,%2,%3};\n"
        : "+f"(d.x), "+f"(d.y), "+f"(d.z), "+f"(d.w)
        : "r"(a[0]), "r"(a[1]), "r"(a[2]), "r"(a[3]), "r"(b[0]), "r"(b[1]));
}
// bf16 m16n8k16 (used by k1)
__device__ __forceinline__ void mma16bf(float4& d, const uint32_t* a, const uint32_t* b) {
    asm volatile(
        "mma.sync.aligned.m16n8k16.row.col.f32.bf16.bf16.f32 "
        "{%0,%1,%2,%3},{%4,%5,%6,%7},{%8,%9},{%0,%1,%2,%3};\n"
        : "+f"(d.x), "+f"(d.y), "+f"(d.z), "+f"(d.w)
        : "r"(a[0]), "r"(a[1]), "r"(a[2]), "r"(a[3]), "r"(b[0]), "r"(b[1]));
}

// ---------------- K0: constants + W build (bf16) + C fragment permute ----------------
__global__ void k0_prep(const float* __restrict__ lnr, const float* __restrict__ imag,
                        const float* __restrict__ Bm, const float* __restrict__ Cm) {
    int j = blockIdx.x;
    int tid = threadIdx.x;
    if (j < 128) {
        int n = j & 63;
        float ar = -expf(lnr[n]);
        float ai = imag[n];
        float e  = expf(ar);
        float2 abar = make_float2(e * cosf(ai), e * sinf(ai));
        float2 num = make_float2(abar.x - 1.0f, abar.y);
        float inv = 1.0f / (ar * ar + ai * ai);
        float2 coef = make_float2((num.x * ar + num.y * ai) * inv,
                                  (num.y * ar - num.x * ai) * inv);
        float s = (j < NS) ? coef.x : coef.y;
        for (int k = tid; k < DM; k += blockDim.x)
            g_Wh[(size_t)j * DM + k] = __float2bfloat16_rn(s * Bm[(size_t)n * DM + k]);
        if (j == 0 && tid < NS) {
            int nn = tid;
            float ar2 = -expf(lnr[nn]);
            float ai2 = imag[nn];
            float e2  = expf(ar2);
            float2 ab = make_float2(e2 * cosf(ai2), e2 * sinf(ai2));
            g_abar[nn] = ab;
            float2 p = make_float2(1.0f, 0.0f);
            for (int k = 0; k <= CT; k++) {
                g_apow[k * NS + nn] = p;
                p = cmul(p, ab);
            }
        }
    } else {
        int o = (j - 128) * 256 + tid;       // 0..65535
        int q    = o & 3;
        int lane = (o >> 2) & 31;
        int ksb  = (o >> 7) & 3;
        int nt   = (o >> 9) & 7;
        int s    = o >> 12;                  // 0..15
        int cq = lane & 3, lq = lane >> 2;
        int d = s * 64 + nt * 8 + lq;
        int k = 8 * (2 * ksb + (q >> 1)) + cq + 4 * (q & 1);
        g_Ct[o] = __uint_as_float(f2tf(Cm[(size_t)d * NS + k]));
    }
}

// ---------------- K1: bf16 MMA Bu-GEMM (128x128, K=1024) + local scan ----------------
#define KC 32
#define HSTR 40                 // bf16 units per row
#define K1_SMEM 65536           // Bu 128*128*4 = 64KB dominates (tiles = 40KB)

__global__ __launch_bounds__(256, 2) void k1_bu_scan(const float* __restrict__ u) {
    extern __shared__ char smc[];
    __nv_bfloat16* As0 = (__nv_bfloat16*)smc;                    // 10240B each
    __nv_bfloat16* As1 = (__nv_bfloat16*)(smc + 10240);
    __nv_bfloat16* Bs0 = (__nv_bfloat16*)(smc + 20480);
    __nv_bfloat16* Bs1 = (__nv_bfloat16*)(smc + 30720);
    float* Bu = (float*)smc;                                     // alias, used after mainloop

    int chunk = blockIdx.x, b = blockIdx.y;
    int tid = threadIdx.x;
    int lane = tid & 31, warp = tid >> 5;
    int wm = warp & 1, wn = warp >> 1;
    int m0 = wm * 64, n0 = wn * 32;
    int lq = lane >> 2, cq = lane & 3;

    const float* up = u + ((size_t)(b * LSEQ + chunk * CT)) * DM;

    float4 acc[4][4];
#pragma unroll
    for (int i = 0; i < 4; i++)
#pragma unroll
        for (int j = 0; j < 4; j++) acc[i][j] = make_float4(0.f, 0.f, 0.f, 0.f);

    float4 rA[4];
    uint2  rW[4];
    int lrow[4], lkq[4];
#pragma unroll
    for (int i = 0; i < 4; i++) {
        int lin = tid + i * 256;
        lrow[i] = lin >> 3;          // 0..127
        lkq[i] = (lin & 7) * 4;      // 0,4,...,28
    }

    // preload stage 0
#pragma unroll
    for (int i = 0; i < 4; i++) {
        rA[i] = *(const float4*)(up + (size_t)lrow[i] * DM + lkq[i]);
        rW[i] = *(const uint2*)(g_Wh + (size_t)lrow[i] * DM + lkq[i]);
    }
#pragma unroll
    for (int i = 0; i < 4; i++) {
        uint2 a;
        a.x = f2bf2(rA[i].x, rA[i].y);
        a.y = f2bf2(rA[i].z, rA[i].w);
        *(uint2*)(As0 + lrow[i] * HSTR + lkq[i]) = a;
        *(uint2*)(Bs0 + lrow[i] * HSTR + lkq[i]) = rW[i];
    }
    __syncthreads();

    for (int s = 0; s < DM / KC; s++) {
        __nv_bfloat16* Ac = (s & 1) ? As1 : As0;
        __nv_bfloat16* Bc = (s & 1) ? Bs1 : Bs0;
        __nv_bfloat16* An = (s & 1) ? As0 : As1;
        __nv_bfloat16* Bn = (s & 1) ? Bs0 : Bs1;
        if (s + 1 < DM / KC) {
            int k0 = (s + 1) * KC;
#pragma unroll
            for (int i = 0; i < 4; i++) {
                rA[i] = *(const float4*)(up + (size_t)lrow[i] * DM + k0 + lkq[i]);
                rW[i] = *(const uint2*)(g_Wh + (size_t)lrow[i] * DM + k0 + lkq[i]);
            }
        }
        const uint32_t* Au = (const uint32_t*)Ac;   // 20 words per row
        const uint32_t* Bv = (const uint32_t*)Bc;
#pragma unroll
        for (int ks = 0; ks < 2; ks++) {            // two k16 steps per stage
            int kb = ks * 8;
            uint32_t af[4][4], bf[4][2];
#pragma unroll
            for (int mt = 0; mt < 4; mt++) {
                int r = m0 + mt * 16 + lq;
                af[mt][0] = Au[r * 20 + kb + cq];
                af[mt][1] = Au[(r + 8) * 20 + kb + cq];
                af[mt][2] = Au[r * 20 + kb + cq + 4];
                af[mt][3] = Au[(r + 8) * 20 + kb + cq + 4];
            }
#pragma unroll
            for (int nt = 0; nt < 4; nt++) {
                int c = n0 + nt * 8 + lq;
                bf[nt][0] = Bv[c * 20 + kb + cq];
                bf[nt][1] = Bv[c * 20 + kb + cq + 4];
            }
#pragma unroll
            for (int mt = 0; mt < 4; mt++)
#pragma unroll
                for (int nt = 0; nt < 4; nt++)
                    mma16bf(acc[mt][nt], af[mt], bf[nt]);
        }
        if (s + 1 < DM / KC) {
#pragma unroll
            for (int i = 0; i < 4; i++) {
                uint2 a;
                a.x = f2bf2(rA[i].x, rA[i].y);
                a.y = f2bf2(rA[i].z, rA[i].w);
                *(uint2*)(An + lrow[i] * HSTR + lkq[i]) = a;
                *(uint2*)(Bn + lrow[i] * HSTR + lkq[i]) = rW[i];
            }
        }
        __syncthreads();
    }

    // write Bu tile to smem (aliases the bf16 tiles — all reads done at last sync)
#pragma unroll
    for (int mt = 0; mt < 4; mt++) {
        int r = m0 + mt * 16 + lq;
#pragma unroll
        for (int nt = 0; nt < 4; nt++) {
            int c = n0 + nt * 8 + cq * 2;
            *(float2*)(Bu + r * 128 + c)       = make_float2(acc[mt][nt].x, acc[mt][nt].y);
            *(float2*)(Bu + (r + 8) * 128 + c) = make_float2(acc[mt][nt].z, acc[mt][nt].w);
        }
    }
    __syncthreads();

    // local scan: 64 states, 1 thread each; store REAL part only
    if (tid < NS) {
        float2 ab = g_abar[tid];
        float hr = 0.0f, hi = 0.0f;
        float* outp = g_hr + ((size_t)(b * LSEQ + chunk * CT)) * NS + tid;
#pragma unroll 4
        for (int t = 0; t < CT; t++) {
            float xr = Bu[t * 128 + tid];
            float xi = Bu[t * 128 + 64 + tid];
            float nr = fmaf(ab.x, hr, fmaf(-ab.y, hi, xr));
            float ni = fmaf(ab.x, hi, fmaf( ab.y, hr, xi));
            hr = nr; hi = ni;
            outp[(size_t)t * NS] = hr;
        }
        g_last[(b * NC + chunk) * NS + tid] = make_float2(hr, hi);
    }
}

// ---------------- K2: cross-chunk carry scan (8 blocks, prefetched) ----------------
__global__ void k2_carry() {
    int b = blockIdx.x;          // 8 blocks
    int n = threadIdx.x;         // 64 threads
    float2 p = g_apow[CT * NS + n];
    float2 S[NC];
#pragma unroll
    for (int c = 0; c < NC; c++) S[c] = g_last[(b * NC + c) * NS + n];
    float2 H = make_float2(0.0f, 0.0f);
#pragma unroll
    for (int c = 0; c < NC; c++) {
        g_carry[(b * NC + c) * NS + n] = H;
        float2 t = cmul(p, H);
        H = make_float2(t.x + S[c].x, t.y + S[c].y);
    }
}

// ---------------- K3: mma readout -> smem exchange -> coalesced residual+LN ----------------
// (proven R9 form: 512 threads, 32 tokens/block, warp owns 64-wide d-slice)
#define XSTR 1036
#define K3_SMEM ((32 * 68 + 32 * XSTR) * 4)

__global__ __launch_bounds__(512, 1) void k3_readout(const float* __restrict__ u,
                                                     const float* __restrict__ Dv,
                                                     const float* __restrict__ gamma,
                                                     const float* __restrict__ beta,
                                                     float* __restrict__ out) {
    extern __shared__ float sm3[];
    float* Rs = sm3;                 // [32][68] tf32 bits
    float* X  = sm3 + 32 * 68;       // [32][XSTR] y values

    int g = blockIdx.x, b = blockIdx.y;
    int chunk = g >> 2, t0 = (g & 3) * 32;
    int tid = threadIdx.x;
    int lane = tid & 31, warp = tid >> 5;
    int lq = lane >> 2, cq = lane & 3;
    size_t tokbase = (size_t)b * LSEQ + (size_t)chunk * CT + t0;

    // build Rs[t][n] = tf32(Re(a^{t0+t+1} * H) + hr_local)
    {
        int n = tid & 63, tq = tid >> 6;    // 8 token groups
        float2 H = g_carry[(b * NC + chunk) * NS + n];
        const float* hp = g_hr + tokbase * NS;
#pragma unroll
        for (int t = tq; t < 32; t += 8) {
            float lv = hp[(size_t)t * NS + n];
            float2 pw = g_apow[(t0 + t + 1) * NS + n];
            float v = fmaf(pw.x, H.x, fmaf(-pw.y, H.y, lv));
            Rs[t * 68 + n] = __uint_as_float(f2tf(v));
        }
    }
    __syncthreads();

    float4 acc[2][8];
#pragma unroll
    for (int mt = 0; mt < 2; mt++)
#pragma unroll
        for (int nt = 0; nt < 8; nt++) acc[mt][nt] = make_float4(0.f, 0.f, 0.f, 0.f);

    const uint32_t* Ru = (const uint32_t*)Rs;
    const uint4* Ct = (const uint4*)g_Ct;   // i = warp*1024 + nt*128 + ksb*32 + lane
    int cbase = warp * 1024 + lane;

#pragma unroll
    for (int ksb = 0; ksb < 4; ksb++) {
        uint32_t af[2][2][4];
#pragma unroll
        for (int ko = 0; ko < 2; ko++) {
            int kb = (ksb * 2 + ko) * 8;
#pragma unroll
            for (int mt = 0; mt < 2; mt++) {
                int r = mt * 16 + lq;
                af[ko][mt][0] = Ru[r * 68 + kb + cq];
                af[ko][mt][1] = Ru[(r + 8) * 68 + kb + cq];
                af[ko][mt][2] = Ru[r * 68 + kb + cq + 4];
                af[ko][mt][3] = Ru[(r + 8) * 68 + kb + cq + 4];
            }
        }
        uint4 Cf = Ct[cbase + ksb * 32];
#pragma unroll
        for (int nt = 0; nt < 8; nt++) {
            uint4 cur = Cf;
            if (nt < 7)
                Cf = Ct[cbase + (nt + 1) * 128 + ksb * 32];
            uint32_t b0[2] = {cur.x, cur.y};
            uint32_t b1[2] = {cur.z, cur.w};
#pragma unroll
            for (int mt = 0; mt < 2; mt++) {
                mma8(acc[mt][nt], af[0][mt], b0);
                mma8(acc[mt][nt], af[1][mt], b1);
            }
        }
    }

    // stage y into X
    int d0w = warp * 64;
#pragma unroll
    for (int nt = 0; nt < 8; nt++) {
        int d = d0w + nt * 8 + cq * 2;
#pragma unroll
        for (int mt = 0; mt < 2; mt++) {
            int r1 = mt * 16 + lq;
            *(float2*)(X + r1 * XSTR + d)       = make_float2(acc[mt][nt].x, acc[mt][nt].y);
            *(float2*)(X + (r1 + 8) * XSTR + d) = make_float2(acc[mt][nt].z, acc[mt][nt].w);
        }
    }
    __syncthreads();

    // coalesced residual + LN: warp w handles token rows 2w, 2w+1
#pragma unroll
    for (int rr = 0; rr < 2; rr++) {
        int r = warp * 2 + rr;
        const float* up = u + (tokbase + r) * DM;
        float* op = out + (tokbase + r) * DM;
        float4 xv[8];
        float s = 0.f, q = 0.f;
#pragma unroll
        for (int i = 0; i < 8; i++) {
            int d = (lane + i * 32) * 4;
            float4 uu = *(const float4*)(up + d);
            float4 D4 = *(const float4*)(Dv + d);
            float4 y  = *(float4*)(X + r * XSTR + d);
            float4 x;
            x.x = fmaf(uu.x, 1.0f + D4.x, y.x);
            x.y = fmaf(uu.y, 1.0f + D4.y, y.y);
            x.z = fmaf(uu.z, 1.0f + D4.z, y.z);
            x.w = fmaf(uu.w, 1.0f + D4.w, y.w);
            xv[i] = x;
            s += x.x + x.y + x.z + x.w;
            q += x.x * x.x + x.y * x.y + x.z * x.z + x.w * x.w;
        }
#pragma unroll
        for (int o = 16; o > 0; o >>= 1) {
            s += __shfl_xor_sync(0xffffffffu, s, o);
            q += __shfl_xor_sync(0xffffffffu, q, o);
        }
        float mu = s * (1.0f / DM);
        float var = q * (1.0f / DM) - mu * mu;
        float rstd = rsqrtf(var + LN_EPS);
#pragma unroll
        for (int i = 0; i < 8; i++) {
            int d = (lane + i * 32) * 4;
            float4 gg = *(const float4*)(gamma + d);
            float4 bb = *(const float4*)(beta + d);
            float4 v = xv[i], o4;
            o4.x = fmaf((v.x - mu) * rstd, gg.x, bb.x);
            o4.y = fmaf((v.y - mu) * rstd, gg.y, bb.y);
            o4.z = fmaf((v.z - mu) * rstd, gg.z, bb.z);
            o4.w = fmaf((v.w - mu) * rstd, gg.w, bb.w);
            *(float4*)(op + d) = o4;
        }
    }
}

// ---------------- launch ----------------
extern "C" void kernel_launch(void* const* d_in, const int* in_sizes, int n_in,
                              void* d_out, int out_size) {
    const float* u     = (const float*)d_in[0];
    const float* lnr   = (const float*)d_in[1];
    const float* imagv = (const float*)d_in[2];
    const float* Bm    = (const float*)d_in[3];
    const float* Cm    = (const float*)d_in[4];
    const float* Dv    = (const float*)d_in[5];
    const float* gamma = (const float*)d_in[6];
    const float* beta  = (const float*)d_in[7];
    float* out = (float*)d_out;

    cudaFuncSetAttribute(k1_bu_scan, cudaFuncAttributeMaxDynamicSharedMemorySize, K1_SMEM);
    cudaFuncSetAttribute(k3_readout, cudaFuncAttributeMaxDynamicSharedMemorySize, K3_SMEM);

    k0_prep<<<384, 256>>>(lnr, imagv, Bm, Cm);
    k1_bu_scan<<<dim3(NC, BSZ), 256, K1_SMEM>>>(u);
    k2_carry<<<8, 64>>>();
    k3_readout<<<dim3(NC * 4, BSZ), 512, K3_SMEM>>>(u, Dv, gamma, beta, out);
}